// round 8
// baseline (speedup 1.0000x reference)
#include <cuda_runtime.h>
#include <math.h>
#include <stdint.h>
#include <stddef.h>

// Problem constants
#define B_   16
#define T_   257          // L+1
#define H_   1024
#define V_   1024
#define S_   512
#define E_   512
#define ENC2_ 1024
#define SOS_ 1
#define EOS_ 2
#define NCTA 128          // persistent recurrence grid (<= SM count -> co-resident)

// ---------------------------------------------------------------------------
// Device scratch (static; no cudaMalloc allowed)
// ---------------------------------------------------------------------------
__device__ float d_P0[(size_t)V_ * 4096];             // emb@W_ih0[:, :E]^T + b_ih0 + b_hh0
__device__ float d_hbuf[3][2][B_ * H_];               // double-buffered h per layer
__device__ float d_hs[(size_t)B_ * T_ * H_];          // top-layer outputs
__device__ float d_scores[(size_t)B_ * T_ * S_];      // attention scores -> probs
__device__ float d_ctx[(size_t)B_ * T_ * H_];         // attention context
__device__ float d_hidden[(size_t)B_ * T_ * H_];      // MLP hidden
__device__ float d_logits[(size_t)B_ * T_ * V_];      // logits
__device__ float d_nll[B_ * T_];
__device__ unsigned d_bar_cnt;
__device__ volatile unsigned d_bar_gen;

// ---------------------------------------------------------------------------
// Init: zero h buffers + barrier state (runs every launch / graph replay)
// ---------------------------------------------------------------------------
__global__ void init_k() {
    int i = blockIdx.x * blockDim.x + threadIdx.x;
    if (i == 0) { d_bar_cnt = 0; d_bar_gen = 0; }
    float* h = &d_hbuf[0][0][0];
    const int n = 3 * 2 * B_ * H_;
    for (int j = i; j < n; j += gridDim.x * blockDim.x) h[j] = 0.f;
}

// ---------------------------------------------------------------------------
// Grid-wide barrier (monotone arrival counter, reset each launch by init_k)
// ---------------------------------------------------------------------------
__device__ __forceinline__ void gridsync(unsigned& lgen) {
    __syncthreads();
    if (threadIdx.x == 0) {
        __threadfence();
        unsigned target = ++lgen;
        unsigned arrived = atomicAdd(&d_bar_cnt, 1u) + 1u;
        if (arrived == target * (unsigned)NCTA) {
            d_bar_gen = target;                    // release
        } else {
            while (d_bar_gen < target) { }         // volatile spin
        }
        __threadfence();
    }
    __syncthreads();
}

__device__ __forceinline__ float sigmoidf_(float x) { return 1.f / (1.f + __expf(-x)); }

// 4 weight rows x 2 batch cols dot over n4 float4 chunks
__device__ __forceinline__ void dot42(const float* __restrict__ W, int j0,
                                      const float* __restrict__ ha,
                                      const float* __restrict__ hb,
                                      int k0, int n4, float acc[4][2]) {
    const float4* w0 = (const float4*)(W + (size_t)(j0 + 0) * H_ + k0);
    const float4* w1 = (const float4*)(W + (size_t)(j0 + 1) * H_ + k0);
    const float4* w2 = (const float4*)(W + (size_t)(j0 + 2) * H_ + k0);
    const float4* w3 = (const float4*)(W + (size_t)(j0 + 3) * H_ + k0);
    const float4* xa = (const float4*)(ha + k0);
    const float4* xb = (const float4*)(hb + k0);
    float a00=0.f,a01=0.f,a10=0.f,a11=0.f,a20=0.f,a21=0.f,a30=0.f,a31=0.f;
#pragma unroll 4
    for (int i = 0; i < n4; ++i) {
        float4 a = xa[i], b = xb[i];
        float4 w = w0[i];
        a00 += w.x*a.x; a00 += w.y*a.y; a00 += w.z*a.z; a00 += w.w*a.w;
        a01 += w.x*b.x; a01 += w.y*b.y; a01 += w.z*b.z; a01 += w.w*b.w;
        w = w1[i];
        a10 += w.x*a.x; a10 += w.y*a.y; a10 += w.z*a.z; a10 += w.w*a.w;
        a11 += w.x*b.x; a11 += w.y*b.y; a11 += w.z*b.z; a11 += w.w*b.w;
        w = w2[i];
        a20 += w.x*a.x; a20 += w.y*a.y; a20 += w.z*a.z; a20 += w.w*a.w;
        a21 += w.x*b.x; a21 += w.y*b.y; a21 += w.z*b.z; a21 += w.w*b.w;
        w = w3[i];
        a30 += w.x*a.x; a30 += w.y*a.y; a30 += w.z*a.z; a30 += w.w*a.w;
        a31 += w.x*b.x; a31 += w.y*b.y; a31 += w.z*b.z; a31 += w.w*b.w;
    }
    acc[0][0]=a00; acc[0][1]=a01; acc[1][0]=a10; acc[1][1]=a11;
    acc[2][0]=a20; acc[2][1]=a21; acc[3][0]=a30; acc[3][1]=a31;
}

// ---------------------------------------------------------------------------
// Persistent LSTM recurrence: 257 steps, 3 layers, grid barrier per layer.
// CTA owns h-units [cta*8, cta*8+8) across all 4 gates and all 16 batches.
// 128 threads = kg(2) x jt(8 -> 4 rows each) x bt(8 -> 2 batches each).
// ---------------------------------------------------------------------------
__global__ __launch_bounds__(128, 1) void recur_k(
    const int* __restrict__ tokens,
    const float* __restrict__ Whh0,
    const float* __restrict__ Wih1, const float* __restrict__ Whh1,
    const float* __restrict__ Wih2, const float* __restrict__ Whh2,
    const float* __restrict__ bih1, const float* __restrict__ bhh1,
    const float* __restrict__ bih2, const float* __restrict__ bhh2) {

    __shared__ float gp[2][32][16];     // [kg][local gate row][batch] partials
    __shared__ float c_s[3][128];       // cell state [layer][uu*16+bb]

    const int tid = threadIdx.x, cta = blockIdx.x;
    for (int i = tid; i < 3 * 128; i += 128) (&c_s[0][0])[i] = 0.f;

    const int kg = tid >> 6;            // 0/1
    const int r  = tid & 63;
    const int jt = r >> 3;              // 0..7
    const int bt = r & 7;               // 0..7
    const int g  = jt >> 1;             // gate for GEMM rows
    const int u4 = (jt & 1) * 4;
    const int j0 = g * 1024 + cta * 8 + u4;   // global weight row
    const int l0 = g * 8 + u4;                // local gp row
    const int b0 = bt * 2;

    const int uu = tid >> 4;            // update-phase unit 0..7
    const int bb = tid & 15;            // update-phase batch 0..15
    const int ucol = cta * 8 + uu;

    unsigned lgen = 0;
    __syncthreads();

    float acc[4][2];

    for (int t = 0; t < T_; ++t) {
        const int ob = t & 1, nb = ob ^ 1;

        // ---------------- layer 0: P0[tok] + h0_old @ Whh0^T ----------------
        {
            const float* H0 = d_hbuf[0][ob];
            dot42(Whh0, j0, H0 + b0 * H_, H0 + (b0 + 1) * H_, kg * 512, 128, acc);
#pragma unroll
            for (int i = 0; i < 4; ++i) {
                gp[kg][l0 + i][b0]     = acc[i][0];
                gp[kg][l0 + i][b0 + 1] = acc[i][1];
            }
        }
        __syncthreads();
        {
            int tok = (t == 0) ? SOS_ : tokens[bb * 256 + (t - 1)];
            const float* p0 = d_P0 + (size_t)tok * 4096;
            float gv[4];
#pragma unroll
            for (int gg = 0; gg < 4; ++gg)
                gv[gg] = gp[0][gg * 8 + uu][bb] + gp[1][gg * 8 + uu][bb]
                       + p0[gg * 1024 + ucol];
            float ig = sigmoidf_(gv[0]);
            float fg = sigmoidf_(gv[1]);
            float gt = tanhf(gv[2]);
            float og = sigmoidf_(gv[3]);
            float cc = fg * c_s[0][uu * 16 + bb] + ig * gt;
            c_s[0][uu * 16 + bb] = cc;
            d_hbuf[0][nb][bb * H_ + ucol] = og * tanhf(cc);
        }
        gridsync(lgen);

        // ---------------- layer 1: h0_new @ Wih1^T + h1_old @ Whh1^T --------
        {
            const float* W  = kg ? Whh1 : Wih1;
            const float* Hs = kg ? d_hbuf[1][ob] : d_hbuf[0][nb];
            dot42(W, j0, Hs + b0 * H_, Hs + (b0 + 1) * H_, 0, 256, acc);
#pragma unroll
            for (int i = 0; i < 4; ++i) {
                gp[kg][l0 + i][b0]     = acc[i][0];
                gp[kg][l0 + i][b0 + 1] = acc[i][1];
            }
        }
        __syncthreads();
        {
            float gv[4];
#pragma unroll
            for (int gg = 0; gg < 4; ++gg) {
                int j = gg * 1024 + ucol;
                gv[gg] = gp[0][gg * 8 + uu][bb] + gp[1][gg * 8 + uu][bb]
                       + bih1[j] + bhh1[j];
            }
            float ig = sigmoidf_(gv[0]);
            float fg = sigmoidf_(gv[1]);
            float gt = tanhf(gv[2]);
            float og = sigmoidf_(gv[3]);
            float cc = fg * c_s[1][uu * 16 + bb] + ig * gt;
            c_s[1][uu * 16 + bb] = cc;
            d_hbuf[1][nb][bb * H_ + ucol] = og * tanhf(cc);
        }
        gridsync(lgen);

        // ---------------- layer 2: h1_new @ Wih2^T + h2_old @ Whh2^T --------
        {
            const float* W  = kg ? Whh2 : Wih2;
            const float* Hs = kg ? d_hbuf[2][ob] : d_hbuf[1][nb];
            dot42(W, j0, Hs + b0 * H_, Hs + (b0 + 1) * H_, 0, 256, acc);
#pragma unroll
            for (int i = 0; i < 4; ++i) {
                gp[kg][l0 + i][b0]     = acc[i][0];
                gp[kg][l0 + i][b0 + 1] = acc[i][1];
            }
        }
        __syncthreads();
        {
            float gv[4];
#pragma unroll
            for (int gg = 0; gg < 4; ++gg) {
                int j = gg * 1024 + ucol;
                gv[gg] = gp[0][gg * 8 + uu][bb] + gp[1][gg * 8 + uu][bb]
                       + bih2[j] + bhh2[j];
            }
            float ig = sigmoidf_(gv[0]);
            float fg = sigmoidf_(gv[1]);
            float gt = tanhf(gv[2]);
            float og = sigmoidf_(gv[3]);
            float cc = fg * c_s[2][uu * 16 + bb] + ig * gt;
            c_s[2][uu * 16 + bb] = cc;
            float hh = og * tanhf(cc);
            d_hbuf[2][nb][bb * H_ + ucol] = hh;
            d_hs[((size_t)bb * T_ + t) * H_ + ucol] = hh;
        }
        gridsync(lgen);
    }
}

// ---------------------------------------------------------------------------
// Generic tiled SGEMM.  TRANSB=1: C = A[MxK] * B[NxK]^T ; TRANSB=0: C = A * B[KxN]
// 64x64 tile, BK=16, 256 threads, 4x4 micro-tile. Only M may be ragged.
// ---------------------------------------------------------------------------
template <int TRANSB, int ACCUM, int DOTANH>
__global__ void gemm_k(const float* __restrict__ A, const float* __restrict__ B,
                       float* __restrict__ C,
                       int M, int N, int K, int lda, int ldb, int ldc,
                       long long sA, long long sB, long long sC,
                       const float* __restrict__ bias1,
                       const float* __restrict__ bias2) {
    A += (long long)blockIdx.z * sA;
    B += (long long)blockIdx.z * sB;
    C += (long long)blockIdx.z * sC;

    __shared__ float As[16][68];
    __shared__ float Bs[16][68];

    const int m0 = blockIdx.y * 64, n0 = blockIdx.x * 64;
    const int tid = threadIdx.x;
    const int ty = tid >> 4, tx = tid & 15;
    const int lr = tid >> 2;              // 0..63
    const int lk = (tid & 3) << 2;        // 0,4,8,12

    float acc[4][4] = {};

    for (int kt = 0; kt < K; kt += 16) {
        float4 av = make_float4(0.f, 0.f, 0.f, 0.f);
        if (m0 + lr < M) av = *(const float4*)(A + (size_t)(m0 + lr) * lda + kt + lk);
        As[lk + 0][lr] = av.x; As[lk + 1][lr] = av.y;
        As[lk + 2][lr] = av.z; As[lk + 3][lr] = av.w;
        if (TRANSB) {
            float4 bv = *(const float4*)(B + (size_t)(n0 + lr) * ldb + kt + lk);
            Bs[lk + 0][lr] = bv.x; Bs[lk + 1][lr] = bv.y;
            Bs[lk + 2][lr] = bv.z; Bs[lk + 3][lr] = bv.w;
        } else {
            int bk = tid >> 4, bn = (tid & 15) << 2;
            float4 bv = *(const float4*)(B + (size_t)(kt + bk) * ldb + n0 + bn);
            *(float4*)&Bs[bk][bn] = bv;
        }
        __syncthreads();
#pragma unroll
        for (int kk = 0; kk < 16; ++kk) {
            float4 a = *(const float4*)&As[kk][ty << 2];
            float4 b = *(const float4*)&Bs[kk][tx << 2];
            acc[0][0] += a.x*b.x; acc[0][1] += a.x*b.y; acc[0][2] += a.x*b.z; acc[0][3] += a.x*b.w;
            acc[1][0] += a.y*b.x; acc[1][1] += a.y*b.y; acc[1][2] += a.y*b.z; acc[1][3] += a.y*b.w;
            acc[2][0] += a.z*b.x; acc[2][1] += a.z*b.y; acc[2][2] += a.z*b.z; acc[2][3] += a.z*b.w;
            acc[3][0] += a.w*b.x; acc[3][1] += a.w*b.y; acc[3][2] += a.w*b.z; acc[3][3] += a.w*b.w;
        }
        __syncthreads();
    }

#pragma unroll
    for (int i = 0; i < 4; ++i) {
        int m = m0 + (ty << 2) + i;
        if (m >= M) continue;
#pragma unroll
        for (int j = 0; j < 4; ++j) {
            int n = n0 + (tx << 2) + j;
            float v = acc[i][j];
            if (ACCUM) v += C[(size_t)m * ldc + n];
            if (bias1) v += bias1[n];
            if (bias2) v += bias2[n];
            if (DOTANH) v = tanhf(v);
            C[(size_t)m * ldc + n] = v;
        }
    }
}

// ---------------------------------------------------------------------------
// Row softmax over S_=512 (in place), one block per row
// ---------------------------------------------------------------------------
__global__ void softmax_k() {
    __shared__ float red[256];
    const int tid = threadIdx.x;
    float* x = d_scores + (size_t)blockIdx.x * S_;
    float m = fmaxf(x[tid], x[tid + 256]);
    red[tid] = m; __syncthreads();
    for (int s = 128; s > 0; s >>= 1) {
        if (tid < s) red[tid] = fmaxf(red[tid], red[tid + s]);
        __syncthreads();
    }
    m = red[0]; __syncthreads();
    float e0 = __expf(x[tid] - m), e1 = __expf(x[tid + 256] - m);
    red[tid] = e0 + e1; __syncthreads();
    for (int s = 128; s > 0; s >>= 1) {
        if (tid < s) red[tid] += red[tid + s];
        __syncthreads();
    }
    float inv = 1.f / red[0];
    x[tid] = e0 * inv;
    x[tid + 256] = e1 * inv;
}

// ---------------------------------------------------------------------------
// NLL per row: lse(logits) - logits[target]
// ---------------------------------------------------------------------------
__global__ void nll_k(const int* __restrict__ tokens) {
    __shared__ float red[256];
    const int tid = threadIdx.x;
    const int row = blockIdx.x;
    const int b = row / T_, t = row % T_;
    const float* x = d_logits + (size_t)row * V_;
    float m = -1e30f;
    for (int i = tid; i < V_; i += 256) m = fmaxf(m, x[i]);
    red[tid] = m; __syncthreads();
    for (int s = 128; s > 0; s >>= 1) {
        if (tid < s) red[tid] = fmaxf(red[tid], red[tid + s]);
        __syncthreads();
    }
    m = red[0]; __syncthreads();
    float sum = 0.f;
    for (int i = tid; i < V_; i += 256) sum += __expf(x[i] - m);
    red[tid] = sum; __syncthreads();
    for (int s = 128; s > 0; s >>= 1) {
        if (tid < s) red[tid] += red[tid + s];
        __syncthreads();
    }
    if (tid == 0) {
        int tgt = (t < 256) ? tokens[b * 256 + t] : EOS_;
        d_nll[row] = m + logf(red[0]) - x[tgt];
    }
}

__global__ void mean_k(float* __restrict__ out) {
    __shared__ float red[256];
    const int tid = threadIdx.x;
    float s = 0.f;
    for (int i = tid; i < B_ * T_; i += 256) s += d_nll[i];
    red[tid] = s; __syncthreads();
    for (int st = 128; st > 0; st >>= 1) {
        if (tid < st) red[tid] += red[tid + st];
        __syncthreads();
    }
    if (tid == 0) out[0] = red[0] / (float)(B_ * T_);
}

// ---------------------------------------------------------------------------
extern "C" void kernel_launch(void* const* d_in, const int* in_sizes, int n_in,
                              void* d_out, int out_size) {
    const int*   tokens = (const int*)  d_in[0];
    const float* enc    = (const float*)d_in[1];
    const float* emb    = (const float*)d_in[2];
    const float* Wih0   = (const float*)d_in[3];
    const float* Whh0   = (const float*)d_in[4];
    const float* bih0   = (const float*)d_in[5];
    const float* bhh0   = (const float*)d_in[6];
    const float* Wih1   = (const float*)d_in[7];
    const float* Whh1   = (const float*)d_in[8];
    const float* bih1   = (const float*)d_in[9];
    const float* bhh1   = (const float*)d_in[10];
    const float* Wih2   = (const float*)d_in[11];
    const float* Whh2   = (const float*)d_in[12];
    const float* bih2   = (const float*)d_in[13];
    const float* bhh2   = (const float*)d_in[14];
    const float* W1     = (const float*)d_in[15];
    const float* b1     = (const float*)d_in[16];
    const float* W2     = (const float*)d_in[17];
    const float* b2     = (const float*)d_in[18];
    float* out = (float*)d_out;

    float* P0;      cudaGetSymbolAddress((void**)&P0,      d_P0);
    float* hs;      cudaGetSymbolAddress((void**)&hs,      d_hs);
    float* scores;  cudaGetSymbolAddress((void**)&scores,  d_scores);
    float* ctx;     cudaGetSymbolAddress((void**)&ctx,     d_ctx);
    float* hidden;  cudaGetSymbolAddress((void**)&hidden,  d_hidden);
    float* logits;  cudaGetSymbolAddress((void**)&logits,  d_logits);

    // reset h buffers + barrier
    init_k<<<192, 256>>>();

    // P0[v][j] = emb[v] . Wih0[j][:E] + bih0[j] + bhh0[j]
    gemm_k<1,0,0><<<dim3(64, 16, 1), 256>>>(
        emb, Wih0, P0, 1024, 4096, 512, 512, 1536, 4096, 0, 0, 0, bih0, bhh0);

    // persistent recurrence (all 257 steps)
    recur_k<<<NCTA, 128>>>(tokens, Whh0, Wih1, Whh1, Wih2, Whh2,
                           bih1, bhh1, bih2, bhh2);

    // attention scores: [b] hs[257,1024] * enc[512,1024]^T
    gemm_k<1,0,0><<<dim3(8, 5, 16), 256>>>(
        hs, enc, scores, T_, S_, H_, H_, ENC2_, S_,
        (long long)T_ * H_, (long long)S_ * ENC2_, (long long)T_ * S_,
        nullptr, nullptr);

    softmax_k<<<B_ * T_, 256>>>();

    // context: [b] probs[257,512] * enc[512,1024]
    gemm_k<0,0,0><<<dim3(16, 5, 16), 256>>>(
        scores, enc, ctx, T_, ENC2_, S_, S_, ENC2_, ENC2_,
        (long long)T_ * S_, (long long)S_ * ENC2_, (long long)T_ * ENC2_,
        nullptr, nullptr);

    // hidden = tanh(hs @ W1[:, :H]^T + ctx @ W1[:, H:]^T + b1)
    gemm_k<1,0,0><<<dim3(16, 65, 1), 256>>>(
        hs, W1, hidden, B_ * T_, H_, H_, H_, 2048, H_, 0, 0, 0,
        nullptr, nullptr);
    gemm_k<1,1,1><<<dim3(16, 65, 1), 256>>>(
        ctx, W1 + 1024, hidden, B_ * T_, H_, ENC2_, ENC2_, 2048, H_, 0, 0, 0,
        b1, nullptr);

    // logits = hidden @ W2^T + b2
    gemm_k<1,0,0><<<dim3(16, 65, 1), 256>>>(
        hidden, W2, logits, B_ * T_, V_, H_, H_, H_, V_, 0, 0, 0,
        b2, nullptr);

    nll_k<<<B_ * T_, 256>>>(tokens);
    mean_k<<<1, 256>>>(out);
}

// round 9
// speedup vs baseline: 3.0242x; 3.0242x over previous
#include <cuda_runtime.h>
#include <math.h>
#include <stdint.h>
#include <stddef.h>

#define B_    16
#define T_    257
#define H_    1024
#define V_    1024
#define S_    512
#define E_    512
#define ENC2_ 1024
#define SOS_  1
#define EOS_  2
#define NCTA  128

typedef unsigned long long u64;

// ---------------------------------------------------------------------------
// f32x2 packed-math helpers (Blackwell)
// ---------------------------------------------------------------------------
__device__ __forceinline__ u64 pack2(float v) {
    u64 r; asm("mov.b64 %0, {%1, %1};" : "=l"(r) : "f"(v)); return r;
}
__device__ __forceinline__ void ffma2(u64& d, u64 a, u64 b) {
    asm("fma.rn.f32x2 %0, %1, %2, %0;" : "+l"(d) : "l"(a), "l"(b));
}
__device__ __forceinline__ float2 unpack2(u64 v) {
    float2 f; asm("mov.b64 {%0, %1}, %2;" : "=f"(f.x), "=f"(f.y) : "l"(v)); return f;
}

// ---------------------------------------------------------------------------
// Device scratch (static only)
// ---------------------------------------------------------------------------
__device__ float d_P0[(size_t)V_ * 4096];                 // 16 MB
__device__ float d_Wp[5ull * 128 * 256 * 32 * 4];         // 80 MB packed weight panels
__device__ float d_hT[3][2][H_ * B_];                     // transposed h: [col][b]
__device__ float d_hs[(size_t)B_ * T_ * H_];
__device__ float d_scores[(size_t)B_ * T_ * S_];
__device__ float d_ctx[(size_t)B_ * T_ * H_];
__device__ float d_hidden[(size_t)B_ * T_ * H_];
__device__ float d_logits[(size_t)B_ * T_ * V_];
__device__ float d_nll[B_ * T_];
__device__ unsigned d_bar_cnt;
__device__ volatile unsigned d_bar_gen;

// ---------------------------------------------------------------------------
__global__ void init_k() {
    int i = blockIdx.x * blockDim.x + threadIdx.x;
    if (i == 0) { d_bar_cnt = 0; d_bar_gen = 0; }
    float* h = &d_hT[0][0][0];
    const int n = 3 * 2 * B_ * H_;
    for (int j = i; j < n; j += gridDim.x * blockDim.x) h[j] = 0.f;
}

// Pack one [4096][1024] matrix into per-CTA panels:
// out[((cta*256 + k4)*32 + lane)*4 + kk] = W[(lane>>3)*1024 + cta*8 + (lane&7)][k4*4+kk]
__global__ void pack_k(const float* __restrict__ W, float* __restrict__ out) {
    const int cta = blockIdx.x, kb = blockIdx.y;   // 128 x 8
    const int lane = threadIdx.x & 31, kq = threadIdx.x >> 5;
    const int j = (lane >> 3) * 1024 + cta * 8 + (lane & 7);
#pragma unroll
    for (int i = 0; i < 4; ++i) {
        int k4 = kb * 32 + kq * 4 + i;
        float4 v = *(const float4*)(W + (size_t)j * 1024 + k4 * 4);
        *(float4*)(out + (((size_t)cta * 256 + k4) * 32 + lane) * 4) = v;
    }
}

// ---------------------------------------------------------------------------
__device__ __forceinline__ void gridsync(unsigned& lgen) {
    __syncthreads();
    if (threadIdx.x == 0) {
        __threadfence();
        unsigned target = ++lgen;
        unsigned arrived = atomicAdd(&d_bar_cnt, 1u) + 1u;
        if (arrived == target * (unsigned)NCTA) {
            d_bar_gen = target;
        } else {
            while (d_bar_gen < target) { }
        }
        __threadfence();
    }
    __syncthreads();
}

__device__ __forceinline__ float sigmoidf_(float x) { return 1.f / (1.f + __expf(-x)); }

// linear copy of hT (64KB) into smem xs — coalesced, conflict-free
__device__ __forceinline__ void stage(const float* __restrict__ hT, float* __restrict__ xs) {
    const float4* src = (const float4*)hT;
    float4* dst = (float4*)xs;
#pragma unroll
    for (int i = 0; i < 16; ++i)
        dst[threadIdx.x + 256 * i] = src[threadIdx.x + 256 * i];
}

// accumulate one K=1024 matrix panel: warp kg handles k in [kg*128, kg*128+128)
__device__ __forceinline__ void accum_mat(int m, int cta, int kg, int lane,
                                          const float* __restrict__ xs, u64 acc[8]) {
    const float4* wp = (const float4*)d_Wp
                     + ((size_t)m * 128 + cta) * 8192 + (size_t)kg * 1024;
    const float* xsk = xs + kg * 2048;
#pragma unroll 4
    for (int k4 = 0; k4 < 32; ++k4) {
        float4 w = wp[k4 * 32 + lane];
        const ulonglong2* xr = (const ulonglong2*)(xsk + k4 * 64);
#pragma unroll
        for (int kk = 0; kk < 4; ++kk) {
            u64 wv = pack2(((const float*)&w)[kk]);
            ulonglong2 x0 = xr[kk * 4 + 0];
            ulonglong2 x1 = xr[kk * 4 + 1];
            ulonglong2 x2 = xr[kk * 4 + 2];
            ulonglong2 x3 = xr[kk * 4 + 3];
            ffma2(acc[0], wv, x0.x); ffma2(acc[1], wv, x0.y);
            ffma2(acc[2], wv, x1.x); ffma2(acc[3], wv, x1.y);
            ffma2(acc[4], wv, x2.x); ffma2(acc[5], wv, x2.y);
            ffma2(acc[6], wv, x3.x); ffma2(acc[7], wv, x3.y);
        }
    }
}

// ---------------------------------------------------------------------------
// Persistent LSTM recurrence. 128 CTAs x 256 threads.
// smem: xs[1024][16] (64KB) | gp[8][32][18] (18KB) | c[3][128]
// ---------------------------------------------------------------------------
__global__ __launch_bounds__(256, 1) void recur_k(const int* __restrict__ tokens,
    const float* __restrict__ bih1, const float* __restrict__ bhh1,
    const float* __restrict__ bih2, const float* __restrict__ bhh2) {

    extern __shared__ float smem[];
    float* xs  = smem;                 // 16384 floats
    float* gp  = smem + 16384;         // 4608 floats
    float* c_s = smem + 16384 + 4608;  // 384 floats

    const int tid = threadIdx.x, cta = blockIdx.x;
    for (int i = tid; i < 384; i += 256) c_s[i] = 0.f;

    const int kg = tid >> 5, lane = tid & 31;
    const int uu = (tid >> 4) & 7, bb = tid & 15;   // update-phase mapping (tid<128)
    const int ucol = cta * 8 + uu;

    unsigned lgen = 0;
    __syncthreads();

    u64 acc[8];

    for (int t = 0; t < T_; ++t) {
        const int ob = t & 1, nb = ob ^ 1;

        // ---------------- layer 0 ----------------
        stage(d_hT[0][ob], xs);
        __syncthreads();
#pragma unroll
        for (int p = 0; p < 8; ++p) acc[p] = 0ull;
        accum_mat(0, cta, kg, lane, xs, acc);
        {
            float* g = gp + (kg * 32 + lane) * 18;
#pragma unroll
            for (int p = 0; p < 8; ++p) *(float2*)(g + 2 * p) = unpack2(acc[p]);
        }
        __syncthreads();
        if (tid < 128) {
            int tok = (t == 0) ? SOS_ : tokens[bb * 256 + (t - 1)];
            const float* p0 = d_P0 + (size_t)tok * 4096;
            float gv[4];
#pragma unroll
            for (int g4 = 0; g4 < 4; ++g4) {
                int lrow = g4 * 8 + uu;
                float s = p0[g4 * 1024 + ucol];
#pragma unroll
                for (int k = 0; k < 8; ++k) s += gp[(k * 32 + lrow) * 18 + bb];
                gv[g4] = s;
            }
            float ig = sigmoidf_(gv[0]), fg = sigmoidf_(gv[1]);
            float gt = tanhf(gv[2]),    og = sigmoidf_(gv[3]);
            float cc = fg * c_s[uu * 16 + bb] + ig * gt;
            c_s[uu * 16 + bb] = cc;
            d_hT[0][nb][ucol * 16 + bb] = og * tanhf(cc);
        }
        gridsync(lgen);

        // ---------------- layer 1 ----------------
        stage(d_hT[0][nb], xs);
        __syncthreads();
#pragma unroll
        for (int p = 0; p < 8; ++p) acc[p] = 0ull;
        accum_mat(1, cta, kg, lane, xs, acc);
        __syncthreads();
        stage(d_hT[1][ob], xs);
        __syncthreads();
        accum_mat(2, cta, kg, lane, xs, acc);
        {
            float* g = gp + (kg * 32 + lane) * 18;
#pragma unroll
            for (int p = 0; p < 8; ++p) *(float2*)(g + 2 * p) = unpack2(acc[p]);
        }
        __syncthreads();
        if (tid < 128) {
            float gv[4];
#pragma unroll
            for (int g4 = 0; g4 < 4; ++g4) {
                int lrow = g4 * 8 + uu;
                int j = g4 * 1024 + ucol;
                float s = bih1[j] + bhh1[j];
#pragma unroll
                for (int k = 0; k < 8; ++k) s += gp[(k * 32 + lrow) * 18 + bb];
                gv[g4] = s;
            }
            float ig = sigmoidf_(gv[0]), fg = sigmoidf_(gv[1]);
            float gt = tanhf(gv[2]),    og = sigmoidf_(gv[3]);
            float cc = fg * c_s[128 + uu * 16 + bb] + ig * gt;
            c_s[128 + uu * 16 + bb] = cc;
            d_hT[1][nb][ucol * 16 + bb] = og * tanhf(cc);
        }
        gridsync(lgen);

        // ---------------- layer 2 ----------------
        stage(d_hT[1][nb], xs);
        __syncthreads();
#pragma unroll
        for (int p = 0; p < 8; ++p) acc[p] = 0ull;
        accum_mat(3, cta, kg, lane, xs, acc);
        __syncthreads();
        stage(d_hT[2][ob], xs);
        __syncthreads();
        accum_mat(4, cta, kg, lane, xs, acc);
        {
            float* g = gp + (kg * 32 + lane) * 18;
#pragma unroll
            for (int p = 0; p < 8; ++p) *(float2*)(g + 2 * p) = unpack2(acc[p]);
        }
        __syncthreads();
        if (tid < 128) {
            float gv[4];
#pragma unroll
            for (int g4 = 0; g4 < 4; ++g4) {
                int lrow = g4 * 8 + uu;
                int j = g4 * 1024 + ucol;
                float s = bih2[j] + bhh2[j];
#pragma unroll
                for (int k = 0; k < 8; ++k) s += gp[(k * 32 + lrow) * 18 + bb];
                gv[g4] = s;
            }
            float ig = sigmoidf_(gv[0]), fg = sigmoidf_(gv[1]);
            float gt = tanhf(gv[2]),    og = sigmoidf_(gv[3]);
            float cc = fg * c_s[256 + uu * 16 + bb] + ig * gt;
            c_s[256 + uu * 16 + bb] = cc;
            float hh = og * tanhf(cc);
            d_hT[2][nb][ucol * 16 + bb] = hh;
            d_hs[((size_t)bb * T_ + t) * H_ + ucol] = hh;
        }
        gridsync(lgen);
    }
}

// ---------------------------------------------------------------------------
// Tiled SGEMM with f32x2 micro-kernel. TRANSB=1: C = A * B^T ; else C = A * B
// ---------------------------------------------------------------------------
template <int TRANSB, int ACCUM, int DOTANH>
__global__ void gemm_k(const float* __restrict__ A, const float* __restrict__ B,
                       float* __restrict__ C,
                       int M, int N, int K, int lda, int ldb, int ldc,
                       long long sA, long long sB, long long sC,
                       const float* __restrict__ bias1,
                       const float* __restrict__ bias2) {
    A += (long long)blockIdx.z * sA;
    B += (long long)blockIdx.z * sB;
    C += (long long)blockIdx.z * sC;

    __shared__ float As[16][68];
    __shared__ float Bs[16][68];

    const int m0 = blockIdx.y * 64, n0 = blockIdx.x * 64;
    const int tid = threadIdx.x;
    const int ty = tid >> 4, tx = tid & 15;
    const int lr = tid >> 2;
    const int lk = (tid & 3) << 2;

    u64 acc2[4][2] = {};

    for (int kt = 0; kt < K; kt += 16) {
        float4 av = make_float4(0.f, 0.f, 0.f, 0.f);
        if (m0 + lr < M) av = *(const float4*)(A + (size_t)(m0 + lr) * lda + kt + lk);
        As[lk + 0][lr] = av.x; As[lk + 1][lr] = av.y;
        As[lk + 2][lr] = av.z; As[lk + 3][lr] = av.w;
        if (TRANSB) {
            float4 bv = *(const float4*)(B + (size_t)(n0 + lr) * ldb + kt + lk);
            Bs[lk + 0][lr] = bv.x; Bs[lk + 1][lr] = bv.y;
            Bs[lk + 2][lr] = bv.z; Bs[lk + 3][lr] = bv.w;
        } else {
            int bk = tid >> 4, bn = (tid & 15) << 2;
            float4 bv = *(const float4*)(B + (size_t)(kt + bk) * ldb + n0 + bn);
            *(float4*)&Bs[bk][bn] = bv;
        }
        __syncthreads();
#pragma unroll
        for (int kk = 0; kk < 16; ++kk) {
            float4 a = *(const float4*)&As[kk][ty << 2];
            ulonglong2 b2 = *(const ulonglong2*)&Bs[kk][tx << 2];
            u64 a0 = pack2(a.x), a1 = pack2(a.y), a2 = pack2(a.z), a3 = pack2(a.w);
            ffma2(acc2[0][0], a0, b2.x); ffma2(acc2[0][1], a0, b2.y);
            ffma2(acc2[1][0], a1, b2.x); ffma2(acc2[1][1], a1, b2.y);
            ffma2(acc2[2][0], a2, b2.x); ffma2(acc2[2][1], a2, b2.y);
            ffma2(acc2[3][0], a3, b2.x); ffma2(acc2[3][1], a3, b2.y);
        }
        __syncthreads();
    }

#pragma unroll
    for (int i = 0; i < 4; ++i) {
        int m = m0 + (ty << 2) + i;
        if (m >= M) continue;
        float vj[4];
        float2 u0 = unpack2(acc2[i][0]), u1 = unpack2(acc2[i][1]);
        vj[0] = u0.x; vj[1] = u0.y; vj[2] = u1.x; vj[3] = u1.y;
#pragma unroll
        for (int j = 0; j < 4; ++j) {
            int n = n0 + (tx << 2) + j;
            float v = vj[j];
            if (ACCUM) v += C[(size_t)m * ldc + n];
            if (bias1) v += bias1[n];
            if (bias2) v += bias2[n];
            if (DOTANH) v = tanhf(v);
            C[(size_t)m * ldc + n] = v;
        }
    }
}

// ---------------------------------------------------------------------------
__global__ void softmax_k() {
    __shared__ float red[256];
    const int tid = threadIdx.x;
    float* x = d_scores + (size_t)blockIdx.x * S_;
    float m = fmaxf(x[tid], x[tid + 256]);
    red[tid] = m; __syncthreads();
    for (int s = 128; s > 0; s >>= 1) {
        if (tid < s) red[tid] = fmaxf(red[tid], red[tid + s]);
        __syncthreads();
    }
    m = red[0]; __syncthreads();
    float e0 = __expf(x[tid] - m), e1 = __expf(x[tid + 256] - m);
    red[tid] = e0 + e1; __syncthreads();
    for (int s = 128; s > 0; s >>= 1) {
        if (tid < s) red[tid] += red[tid + s];
        __syncthreads();
    }
    float inv = 1.f / red[0];
    x[tid] = e0 * inv;
    x[tid + 256] = e1 * inv;
}

__global__ void nll_k(const int* __restrict__ tokens) {
    __shared__ float red[256];
    const int tid = threadIdx.x;
    const int row = blockIdx.x;
    const int b = row / T_, t = row % T_;
    const float* x = d_logits + (size_t)row * V_;
    float m = -1e30f;
    for (int i = tid; i < V_; i += 256) m = fmaxf(m, x[i]);
    red[tid] = m; __syncthreads();
    for (int s = 128; s > 0; s >>= 1) {
        if (tid < s) red[tid] = fmaxf(red[tid], red[tid + s]);
        __syncthreads();
    }
    m = red[0]; __syncthreads();
    float sum = 0.f;
    for (int i = tid; i < V_; i += 256) sum += __expf(x[i] - m);
    red[tid] = sum; __syncthreads();
    for (int s = 128; s > 0; s >>= 1) {
        if (tid < s) red[tid] += red[tid + s];
        __syncthreads();
    }
    if (tid == 0) {
        int tgt = (t < 256) ? tokens[b * 256 + t] : EOS_;
        d_nll[row] = m + logf(red[0]) - x[tgt];
    }
}

__global__ void mean_k(float* __restrict__ out) {
    __shared__ float red[256];
    const int tid = threadIdx.x;
    float s = 0.f;
    for (int i = tid; i < B_ * T_; i += 256) s += d_nll[i];
    red[tid] = s; __syncthreads();
    for (int st = 128; st > 0; st >>= 1) {
        if (tid < st) red[tid] += red[tid + st];
        __syncthreads();
    }
    if (tid == 0) out[0] = red[0] / (float)(B_ * T_);
}

// ---------------------------------------------------------------------------
extern "C" void kernel_launch(void* const* d_in, const int* in_sizes, int n_in,
                              void* d_out, int out_size) {
    const int*   tokens = (const int*)  d_in[0];
    const float* enc    = (const float*)d_in[1];
    const float* emb    = (const float*)d_in[2];
    const float* Wih0   = (const float*)d_in[3];
    const float* Whh0   = (const float*)d_in[4];
    const float* bih0   = (const float*)d_in[5];
    const float* bhh0   = (const float*)d_in[6];
    const float* Wih1   = (const float*)d_in[7];
    const float* Whh1   = (const float*)d_in[8];
    const float* bih1   = (const float*)d_in[9];
    const float* bhh1   = (const float*)d_in[10];
    const float* Wih2   = (const float*)d_in[11];
    const float* Whh2   = (const float*)d_in[12];
    const float* bih2   = (const float*)d_in[13];
    const float* bhh2   = (const float*)d_in[14];
    const float* W1     = (const float*)d_in[15];
    const float* b1     = (const float*)d_in[16];
    const float* W2     = (const float*)d_in[17];
    const float* b2     = (const float*)d_in[18];
    float* out = (float*)d_out;

    float* P0;      cudaGetSymbolAddress((void**)&P0,      d_P0);
    float* Wp;      cudaGetSymbolAddress((void**)&Wp,      d_Wp);
    float* hs;      cudaGetSymbolAddress((void**)&hs,      d_hs);
    float* scores;  cudaGetSymbolAddress((void**)&scores,  d_scores);
    float* ctx;     cudaGetSymbolAddress((void**)&ctx,     d_ctx);
    float* hidden;  cudaGetSymbolAddress((void**)&hidden,  d_hidden);
    float* logits;  cudaGetSymbolAddress((void**)&logits,  d_logits);

    static int smem_set = 0;
    if (!smem_set) {
        cudaFuncSetAttribute(recur_k, cudaFuncAttributeMaxDynamicSharedMemorySize,
                             (16384 + 4608 + 384) * 4);
        smem_set = 1;
    }

    init_k<<<192, 256>>>();

    // pack the 5 recurrent matrices into panels
    const size_t MSZ = 128ull * 256 * 32 * 4;
    pack_k<<<dim3(128, 8), 256>>>(Whh0, Wp + 0 * MSZ);
    pack_k<<<dim3(128, 8), 256>>>(Wih1, Wp + 1 * MSZ);
    pack_k<<<dim3(128, 8), 256>>>(Whh1, Wp + 2 * MSZ);
    pack_k<<<dim3(128, 8), 256>>>(Wih2, Wp + 3 * MSZ);
    pack_k<<<dim3(128, 8), 256>>>(Whh2, Wp + 4 * MSZ);

    // P0[v][j] = emb[v] . Wih0[j][:E] + bih0[j] + bhh0[j]
    gemm_k<1,0,0><<<dim3(64, 16, 1), 256>>>(
        emb, Wih0, P0, 1024, 4096, 512, 512, 1536, 4096, 0, 0, 0, bih0, bhh0);

    // persistent recurrence
    recur_k<<<NCTA, 256, (16384 + 4608 + 384) * 4>>>(tokens, bih1, bhh1, bih2, bhh2);

    // attention scores: [b] hs[257,1024] * enc[512,1024]^T
    gemm_k<1,0,0><<<dim3(8, 5, 16), 256>>>(
        hs, enc, scores, T_, S_, H_, H_, ENC2_, S_,
        (long long)T_ * H_, (long long)S_ * ENC2_, (long long)T_ * S_,
        nullptr, nullptr);

    softmax_k<<<B_ * T_, 256>>>();

    // context: [b] probs[257,512] * enc[512,1024]
    gemm_k<0,0,0><<<dim3(16, 5, 16), 256>>>(
        scores, enc, ctx, T_, ENC2_, S_, S_, ENC2_, ENC2_,
        (long long)T_ * S_, (long long)S_ * ENC2_, (long long)T_ * ENC2_,
        nullptr, nullptr);

    // hidden = tanh(hs @ W1[:, :H]^T + ctx @ W1[:, H:]^T + b1)
    gemm_k<1,0,0><<<dim3(16, 65, 1), 256>>>(
        hs, W1, hidden, B_ * T_, H_, H_, H_, 2048, H_, 0, 0, 0,
        nullptr, nullptr);
    gemm_k<1,1,1><<<dim3(16, 65, 1), 256>>>(
        ctx, W1 + 1024, hidden, B_ * T_, H_, ENC2_, ENC2_, 2048, H_, 0, 0, 0,
        b1, nullptr);

    // logits = hidden @ W2^T + b2
    gemm_k<1,0,0><<<dim3(16, 65, 1), 256>>>(
        hidden, W2, logits, B_ * T_, V_, H_, H_, H_, V_, 0, 0, 0,
        b2, nullptr);

    nll_k<<<B_ * T_, 256>>>(tokens);
    mean_k<<<1, 256>>>(out);
}

// round 11
// speedup vs baseline: 3.1877x; 1.0541x over previous
#include <cuda_runtime.h>
#include <math.h>
#include <stdint.h>
#include <stddef.h>

#define B_    16
#define T_    257
#define H_    1024
#define V_    1024
#define S_    512
#define E_    512
#define ENC2_ 1024
#define SOS_  1
#define EOS_  2
#define NCTA  128
#define NTHR  512

typedef unsigned long long u64;

// ---------------------------------------------------------------------------
// f32x2 packed-math helpers
// ---------------------------------------------------------------------------
__device__ __forceinline__ u64 pack2(float v) {
    u64 r; asm("mov.b64 %0, {%1, %1};" : "=l"(r) : "f"(v)); return r;
}
__device__ __forceinline__ void ffma2(u64& d, u64 a, u64 b) {
    asm("fma.rn.f32x2 %0, %1, %2, %0;" : "+l"(d) : "l"(a), "l"(b));
}
__device__ __forceinline__ float2 unpack2(u64 v) {
    float2 f; asm("mov.b64 {%0, %1}, %2;" : "=f"(f.x), "=f"(f.y) : "l"(v)); return f;
}

// cp.async helpers
__device__ __forceinline__ void stage_async(const float* __restrict__ src,
                                            float* __restrict__ dst, int tid) {
#pragma unroll
    for (int i = 0; i < 8; ++i) {
        unsigned u = (unsigned)__cvta_generic_to_shared(dst + (tid + NTHR * i) * 4);
        asm volatile("cp.async.cg.shared.global [%0], [%1], 16;"
                     :: "r"(u), "l"(src + (tid + NTHR * i) * 4));
    }
    asm volatile("cp.async.commit_group;");
}
template <int N> __device__ __forceinline__ void cp_wait() {
    asm volatile("cp.async.wait_group %0;" :: "n"(N));
}

// ---------------------------------------------------------------------------
// Device scratch (static only)
// ---------------------------------------------------------------------------
__device__ float d_P0[(size_t)V_ * 4096];                 // 16 MB
__device__ float d_Wp[5ull * 128 * 256 * 32 * 4];         // 80 MB packed panels
__device__ float d_hT[3][2][H_ * B_];                     // transposed h: [col][b]
__device__ float d_hs[(size_t)B_ * T_ * H_];
__device__ float d_scores[(size_t)B_ * T_ * S_];
__device__ float d_ctx[(size_t)B_ * T_ * H_];
__device__ float d_hidden[(size_t)B_ * T_ * H_];
__device__ float d_logits[(size_t)B_ * T_ * V_];
__device__ float d_nll[B_ * T_];
__device__ unsigned d_bar_cnt;
__device__ volatile unsigned d_bar_gen;

// ---------------------------------------------------------------------------
__global__ void init_k() {
    int i = blockIdx.x * blockDim.x + threadIdx.x;
    if (i == 0) { d_bar_cnt = 0; d_bar_gen = 0; }
    float* h = &d_hT[0][0][0];
    const int n = 3 * 2 * B_ * H_;
    for (int j = i; j < n; j += gridDim.x * blockDim.x) h[j] = 0.f;
}

// Pack one [4096][1024] matrix into per-CTA panels:
// out[((cta*256 + k4)*32 + lane)*4 + kk] = W[(lane>>3)*1024 + cta*8 + (lane&7)][k4*4+kk]
__global__ void pack_k(const float* __restrict__ W, float* __restrict__ out) {
    const int cta = blockIdx.x, kb = blockIdx.y;   // 128 x 8
    const int lane = threadIdx.x & 31, kq = threadIdx.x >> 5;
    const int j = (lane >> 3) * 1024 + cta * 8 + (lane & 7);
#pragma unroll
    for (int i = 0; i < 4; ++i) {
        int k4 = kb * 32 + kq * 4 + i;
        float4 v = *(const float4*)(W + (size_t)j * 1024 + k4 * 4);
        *(float4*)(out + (((size_t)cta * 256 + k4) * 32 + lane) * 4) = v;
    }
}

// ---------------------------------------------------------------------------
__device__ __forceinline__ void gridsync(unsigned& lgen) {
    __syncthreads();
    if (threadIdx.x == 0) {
        __threadfence();
        unsigned target = ++lgen;
        unsigned arrived = atomicAdd(&d_bar_cnt, 1u) + 1u;
        if (arrived == target * (unsigned)NCTA) {
            d_bar_gen = target;
        } else {
            while (d_bar_gen < target) { }
        }
        __threadfence();
    }
    __syncthreads();
}

__device__ __forceinline__ float sigmoidf_(float x) { return 1.f / (1.f + __expf(-x)); }

// One warp accumulates its 64-k slice of one matrix panel into acc[8] (16 batches)
__device__ __forceinline__ void accum_mat(const float* __restrict__ Wm, int cta,
                                          int kg, int lane,
                                          const float* __restrict__ xs, u64 acc[8]) {
    const float4* wp = (const float4*)Wm + ((size_t)cta * 256 + kg * 16) * 32 + lane;
    const float* xsk = xs + kg * 1024;                    // 64 k * 16 floats
#pragma unroll 4
    for (int k4 = 0; k4 < 16; ++k4) {
        float4 w = wp[(size_t)k4 * 32];
        const ulonglong2* xr = (const ulonglong2*)(xsk + k4 * 64);
#pragma unroll
        for (int kk = 0; kk < 4; ++kk) {
            u64 wv = pack2(((const float*)&w)[kk]);
            ulonglong2 x0 = xr[kk * 4 + 0];
            ulonglong2 x1 = xr[kk * 4 + 1];
            ulonglong2 x2 = xr[kk * 4 + 2];
            ulonglong2 x3 = xr[kk * 4 + 3];
            ffma2(acc[0], wv, x0.x); ffma2(acc[1], wv, x0.y);
            ffma2(acc[2], wv, x1.x); ffma2(acc[3], wv, x1.y);
            ffma2(acc[4], wv, x2.x); ffma2(acc[5], wv, x2.y);
            ffma2(acc[6], wv, x3.x); ffma2(acc[7], wv, x3.y);
        }
    }
}

__device__ __forceinline__ void dump(float* __restrict__ gp, int kg, int lane,
                                     const u64 acc[8]) {
    float* g = gp + (kg * 32 + lane) * 18;
#pragma unroll
    for (int p = 0; p < 8; ++p) *(float2*)(g + 2 * p) = unpack2(acc[p]);
}

// sum of 16 k-warp partials for row = gate*8+uu, batch bb
__device__ __forceinline__ float gate_sum(const float* __restrict__ gp, int row, int bb) {
    float s = 0.f;
#pragma unroll
    for (int k = 0; k < 16; ++k) s += gp[(k * 32 + row) * 18 + bb];
    return s;
}

// quad shuffle butterfly -> full i,f,g,o per lane; gate-0 lane writes state
__device__ __forceinline__ void lstm_update(float s, int gate, float* __restrict__ cptr,
                                            float* __restrict__ h1,
                                            float* __restrict__ h2) {
    float b1v = __shfl_xor_sync(0xffffffffu, s,   1);
    float c2v = __shfl_xor_sync(0xffffffffu, s,   2);
    float d2v = __shfl_xor_sync(0xffffffffu, b1v, 2);
    float g0, g1, g2, g3;
    if      (gate == 0) { g0 = s;   g1 = b1v; g2 = c2v; g3 = d2v; }
    else if (gate == 1) { g0 = b1v; g1 = s;   g2 = d2v; g3 = c2v; }
    else if (gate == 2) { g0 = c2v; g1 = d2v; g2 = s;   g3 = b1v; }
    else                { g0 = d2v; g1 = c2v; g2 = b1v; g3 = s;   }
    float ig = sigmoidf_(g0), fg = sigmoidf_(g1);
    float gt = tanhf(g2),     og = sigmoidf_(g3);
    float cc = fg * (*cptr) + ig * gt;
    float hh = og * tanhf(cc);
    if (gate == 0) {
        *cptr = cc;
        *h1 = hh;
        if (h2) *h2 = hh;
    }
}

// ---------------------------------------------------------------------------
// Persistent LSTM recurrence. 128 CTAs x 512 threads.
// smem: xs0[16384] | xs1[16384] | gp[16*32*18=9216] | c_s[384]
// ---------------------------------------------------------------------------
__global__ __launch_bounds__(NTHR, 1) void recur_k(const int* __restrict__ tokens,
    const float* __restrict__ bih1, const float* __restrict__ bhh1,
    const float* __restrict__ bih2, const float* __restrict__ bhh2) {

    extern __shared__ float smem[];
    float* xs0 = smem;
    float* xs1 = smem + 16384;
    float* gp  = smem + 32768;
    float* c_s = smem + 32768 + 9216;

    const int tid = threadIdx.x, cta = blockIdx.x;
    for (int i = tid; i < 384; i += NTHR) c_s[i] = 0.f;

    const int kg   = tid >> 5, lane = tid & 31;   // GEMM mapping: warp = k-slice
    const int quad = tid >> 2, gate = tid & 3;    // update mapping
    const int uu   = quad >> 4, bb = quad & 15;
    const int ucol = cta * 8 + uu;
    const int row  = gate * 8 + uu;
    const int jb   = gate * 1024 + ucol;

    const float bL1 = bih1[jb] + bhh1[jb];
    const float bL2 = bih2[jb] + bhh2[jb];

    const size_t MSZ = 128ull * 256 * 32 * 4;
    const float* W0 = d_Wp;                 // Whh0
    const float* W1 = d_Wp + 1 * MSZ;       // Wih1
    const float* W2 = d_Wp + 2 * MSZ;       // Whh1
    const float* W3 = d_Wp + 3 * MSZ;       // Wih2
    const float* W4 = d_Wp + 4 * MSZ;       // Whh2

    unsigned lgen = 0;
    __syncthreads();

    u64 acc0[8], acc1[8], acc2[8];

    // prologue prefetch: h0_old -> xs0 (group A), h1_old -> xs1 (group B)
    stage_async(d_hT[0][0], xs0, tid);
    stage_async(d_hT[1][0], xs1, tid);

    for (int t = 0; t < T_; ++t) {
        const int ob = t & 1, nb = ob ^ 1;

        // ---- wait A (h0_old in xs0), Whh0 ----
        cp_wait<1>(); __syncthreads();
#pragma unroll
        for (int p = 0; p < 8; ++p) acc0[p] = 0ull;
        accum_mat(W0, cta, kg, lane, xs0, acc0);
        __syncthreads();                          // xs0 free
        stage_async(d_hT[2][ob], xs0, tid);       // group C: h2_old -> xs0

        // ---- wait B (h1_old in xs1), Whh1 (held in regs) ----
        cp_wait<1>(); __syncthreads();
#pragma unroll
        for (int p = 0; p < 8; ++p) acc1[p] = 0ull;
        accum_mat(W2, cta, kg, lane, xs1, acc1);

        // ---- layer 0 update ----
        dump(gp, kg, lane, acc0);
        __syncthreads();
        {
            int tok = (t == 0) ? SOS_ : tokens[bb * 256 + (t - 1)];
            float s = gate_sum(gp, row, bb) + d_P0[(size_t)tok * 4096 + jb];
            lstm_update(s, gate, &c_s[uu * 16 + bb],
                        &d_hT[0][nb][ucol * 16 + bb], nullptr);
        }
        gridsync(lgen);
        stage_async(d_hT[0][nb], xs1, tid);       // group D: h0_new -> xs1

        // ---- wait C (h2_old in xs0), Whh2 (held in regs) ----
        cp_wait<1>(); __syncthreads();
#pragma unroll
        for (int p = 0; p < 8; ++p) acc2[p] = 0ull;
        accum_mat(W4, cta, kg, lane, xs0, acc2);

        // ---- wait D (h0_new in xs1), Wih1 into acc1, layer 1 update ----
        cp_wait<0>(); __syncthreads();
        accum_mat(W1, cta, kg, lane, xs1, acc1);
        dump(gp, kg, lane, acc1);
        __syncthreads();
        {
            float s = gate_sum(gp, row, bb) + bL1;
            lstm_update(s, gate, &c_s[128 + uu * 16 + bb],
                        &d_hT[1][nb][ucol * 16 + bb], nullptr);
        }
        gridsync(lgen);
        stage_async(d_hT[1][nb], xs0, tid);       // group E: h1_new -> xs0

        // ---- wait E (h1_new in xs0), Wih2 into acc2, layer 2 update ----
        cp_wait<0>(); __syncthreads();
        accum_mat(W3, cta, kg, lane, xs0, acc2);
        dump(gp, kg, lane, acc2);
        __syncthreads();
        {
            float s = gate_sum(gp, row, bb) + bL2;
            lstm_update(s, gate, &c_s[256 + uu * 16 + bb],
                        &d_hT[2][nb][ucol * 16 + bb],
                        &d_hs[((size_t)bb * T_ + t) * H_ + ucol]);
        }
        gridsync(lgen);

        if (t + 1 < T_) {                         // prefetch next step's h0/h1
            stage_async(d_hT[0][nb], xs0, tid);   // A'
            stage_async(d_hT[1][nb], xs1, tid);   // B'
        }
    }
}

// ---------------------------------------------------------------------------
// Tiled SGEMM with f32x2 micro-kernel. TRANSB=1: C = A * B^T ; else C = A * B
// ---------------------------------------------------------------------------
template <int TRANSB, int ACCUM, int DOTANH>
__global__ void gemm_k(const float* __restrict__ A, const float* __restrict__ B,
                       float* __restrict__ C,
                       int M, int N, int K, int lda, int ldb, int ldc,
                       long long sA, long long sB, long long sC,
                       const float* __restrict__ bias1,
                       const float* __restrict__ bias2) {
    A += (long long)blockIdx.z * sA;
    B += (long long)blockIdx.z * sB;
    C += (long long)blockIdx.z * sC;

    __shared__ float As[16][68];
    __shared__ float Bs[16][68];

    const int m0 = blockIdx.y * 64, n0 = blockIdx.x * 64;
    const int tid = threadIdx.x;
    const int ty = tid >> 4, tx = tid & 15;
    const int lr = tid >> 2;
    const int lk = (tid & 3) << 2;

    u64 acc2[4][2] = {};

    for (int kt = 0; kt < K; kt += 16) {
        float4 av = make_float4(0.f, 0.f, 0.f, 0.f);
        if (m0 + lr < M) av = *(const float4*)(A + (size_t)(m0 + lr) * lda + kt + lk);
        As[lk + 0][lr] = av.x; As[lk + 1][lr] = av.y;
        As[lk + 2][lr] = av.z; As[lk + 3][lr] = av.w;
        if (TRANSB) {
            float4 bv = *(const float4*)(B + (size_t)(n0 + lr) * ldb + kt + lk);
            Bs[lk + 0][lr] = bv.x; Bs[lk + 1][lr] = bv.y;
            Bs[lk + 2][lr] = bv.z; Bs[lk + 3][lr] = bv.w;
        } else {
            int bk = tid >> 4, bn = (tid & 15) << 2;
            float4 bv = *(const float4*)(B + (size_t)(kt + bk) * ldb + n0 + bn);
            *(float4*)&Bs[bk][bn] = bv;
        }
        __syncthreads();
#pragma unroll
        for (int kk = 0; kk < 16; ++kk) {
            float4 a = *(const float4*)&As[kk][ty << 2];
            ulonglong2 b2 = *(const ulonglong2*)&Bs[kk][tx << 2];
            u64 a0 = pack2(a.x), a1 = pack2(a.y), a2 = pack2(a.z), a3 = pack2(a.w);
            ffma2(acc2[0][0], a0, b2.x); ffma2(acc2[0][1], a0, b2.y);
            ffma2(acc2[1][0], a1, b2.x); ffma2(acc2[1][1], a1, b2.y);
            ffma2(acc2[2][0], a2, b2.x); ffma2(acc2[2][1], a2, b2.y);
            ffma2(acc2[3][0], a3, b2.x); ffma2(acc2[3][1], a3, b2.y);
        }
        __syncthreads();
    }

#pragma unroll
    for (int i = 0; i < 4; ++i) {
        int m = m0 + (ty << 2) + i;
        if (m >= M) continue;
        float vj[4];
        float2 u0 = unpack2(acc2[i][0]), u1 = unpack2(acc2[i][1]);
        vj[0] = u0.x; vj[1] = u0.y; vj[2] = u1.x; vj[3] = u1.y;
#pragma unroll
        for (int j = 0; j < 4; ++j) {
            int n = n0 + (tx << 2) + j;
            float v = vj[j];
            if (ACCUM) v += C[(size_t)m * ldc + n];
            if (bias1) v += bias1[n];
            if (bias2) v += bias2[n];
            if (DOTANH) v = tanhf(v);
            C[(size_t)m * ldc + n] = v;
        }
    }
}

// ---------------------------------------------------------------------------
__global__ void softmax_k() {
    __shared__ float red[256];
    const int tid = threadIdx.x;
    float* x = d_scores + (size_t)blockIdx.x * S_;
    float m = fmaxf(x[tid], x[tid + 256]);
    red[tid] = m; __syncthreads();
    for (int s = 128; s > 0; s >>= 1) {
        if (tid < s) red[tid] = fmaxf(red[tid], red[tid + s]);
        __syncthreads();
    }
    m = red[0]; __syncthreads();
    float e0 = __expf(x[tid] - m), e1 = __expf(x[tid + 256] - m);
    red[tid] = e0 + e1; __syncthreads();
    for (int s = 128; s > 0; s >>= 1) {
        if (tid < s) red[tid] += red[tid + s];
        __syncthreads();
    }
    float inv = 1.f / red[0];
    x[tid] = e0 * inv;
    x[tid + 256] = e1 * inv;
}

__global__ void nll_k(const int* __restrict__ tokens) {
    __shared__ float red[256];
    const int tid = threadIdx.x;
    const int row = blockIdx.x;
    const int b = row / T_, t = row % T_;
    const float* x = d_logits + (size_t)row * V_;
    float m = -1e30f;
    for (int i = tid; i < V_; i += 256) m = fmaxf(m, x[i]);
    red[tid] = m; __syncthreads();
    for (int s = 128; s > 0; s >>= 1) {
        if (tid < s) red[tid] = fmaxf(red[tid], red[tid + s]);
        __syncthreads();
    }
    m = red[0]; __syncthreads();
    float sum = 0.f;
    for (int i = tid; i < V_; i += 256) sum += __expf(x[i] - m);
    red[tid] = sum; __syncthreads();
    for (int s = 128; s > 0; s >>= 1) {
        if (tid < s) red[tid] += red[tid + s];
        __syncthreads();
    }
    if (tid == 0) {
        int tgt = (t < 256) ? tokens[b * 256 + t] : EOS_;
        d_nll[row] = m + logf(red[0]) - x[tgt];
    }
}

__global__ void mean_k(float* __restrict__ out) {
    __shared__ float red[256];
    const int tid = threadIdx.x;
    float s = 0.f;
    for (int i = tid; i < B_ * T_; i += 256) s += d_nll[i];
    red[tid] = s; __syncthreads();
    for (int st = 128; st > 0; st >>= 1) {
        if (tid < st) red[tid] += red[tid + st];
        __syncthreads();
    }
    if (tid == 0) out[0] = red[0] / (float)(B_ * T_);
}

// ---------------------------------------------------------------------------
extern "C" void kernel_launch(void* const* d_in, const int* in_sizes, int n_in,
                              void* d_out, int out_size) {
    const int*   tokens = (const int*)  d_in[0];
    const float* enc    = (const float*)d_in[1];
    const float* emb    = (const float*)d_in[2];
    const float* Wih0   = (const float*)d_in[3];
    const float* Whh0   = (const float*)d_in[4];
    const float* bih0   = (const float*)d_in[5];
    const float* bhh0   = (const float*)d_in[6];
    const float* Wih1   = (const float*)d_in[7];
    const float* bih1   = (const float*)d_in[9];
    const float* Whh1   = (const float*)d_in[8];
    const float* bhh1   = (const float*)d_in[10];
    const float* Wih2   = (const float*)d_in[11];
    const float* Whh2   = (const float*)d_in[12];
    const float* bih2   = (const float*)d_in[13];
    const float* bhh2   = (const float*)d_in[14];
    const float* W1     = (const float*)d_in[15];
    const float* b1     = (const float*)d_in[16];
    const float* W2     = (const float*)d_in[17];
    const float* b2     = (const float*)d_in[18];
    float* out = (float*)d_out;

    float* P0;      cudaGetSymbolAddress((void**)&P0,      d_P0);
    float* Wp;      cudaGetSymbolAddress((void**)&Wp,      d_Wp);
    float* hs;      cudaGetSymbolAddress((void**)&hs,      d_hs);
    float* scores;  cudaGetSymbolAddress((void**)&scores,  d_scores);
    float* ctx;     cudaGetSymbolAddress((void**)&ctx,     d_ctx);
    float* hidden;  cudaGetSymbolAddress((void**)&hidden,  d_hidden);
    float* logits;  cudaGetSymbolAddress((void**)&logits,  d_logits);

    const int RSMEM = (32768 + 9216 + 384) * 4;
    static int smem_set = 0;
    if (!smem_set) {
        cudaFuncSetAttribute(recur_k, cudaFuncAttributeMaxDynamicSharedMemorySize, RSMEM);
        smem_set = 1;
    }

    init_k<<<192, 256>>>();

    // pack the 5 recurrent matrices into panels
    const size_t MSZ = 128ull * 256 * 32 * 4;
    pack_k<<<dim3(128, 8), 256>>>(Whh0, Wp + 0 * MSZ);
    pack_k<<<dim3(128, 8), 256>>>(Wih1, Wp + 1 * MSZ);
    pack_k<<<dim3(128, 8), 256>>>(Whh1, Wp + 2 * MSZ);
    pack_k<<<dim3(128, 8), 256>>>(Wih2, Wp + 3 * MSZ);
    pack_k<<<dim3(128, 8), 256>>>(Whh2, Wp + 4 * MSZ);

    // P0[v][j] = emb[v] . Wih0[j][:E] + bih0[j] + bhh0[j]
    gemm_k<1,0,0><<<dim3(64, 16, 1), 256>>>(
        emb, Wih0, P0, 1024, 4096, 512, 512, 1536, 4096, 0, 0, 0, bih0, bhh0);

    // persistent recurrence
    recur_k<<<NCTA, NTHR, RSMEM>>>(tokens, bih1, bhh1, bih2, bhh2);

    // attention scores: [b] hs[257,1024] * enc[512,1024]^T
    gemm_k<1,0,0><<<dim3(8, 5, 16), 256>>>(
        hs, enc, scores, T_, S_, H_, H_, ENC2_, S_,
        (long long)T_ * H_, (long long)S_ * ENC2_, (long long)T_ * S_,
        nullptr, nullptr);

    softmax_k<<<B_ * T_, 256>>>();

    // context: [b] probs[257,512] * enc[512,1024]
    gemm_k<0,0,0><<<dim3(16, 5, 16), 256>>>(
        scores, enc, ctx, T_, ENC2_, S_, S_, ENC2_, ENC2_,
        (long long)T_ * S_, (long long)S_ * ENC2_, (long long)T_ * ENC2_,
        nullptr, nullptr);

    // hidden = tanh(hs @ W1[:, :H]^T + ctx @ W1[:, H:]^T + b1)
    gemm_k<1,0,0><<<dim3(16, 65, 1), 256>>>(
        hs, W1, hidden, B_ * T_, H_, H_, H_, 2048, H_, 0, 0, 0,
        nullptr, nullptr);
    gemm_k<1,1,1><<<dim3(16, 65, 1), 256>>>(
        ctx, W1 + 1024, hidden, B_ * T_, H_, ENC2_, ENC2_, 2048, H_, 0, 0, 0,
        b1, nullptr);

    // logits = hidden @ W2^T + b2
    gemm_k<1,0,0><<<dim3(16, 65, 1), 256>>>(
        hidden, W2, logits, B_ * T_, V_, H_, H_, H_, V_, 0, 0, 0,
        b2, nullptr);

    nll_k<<<B_ * T_, 256>>>(tokens);
    mean_k<<<1, 256>>>(out);
}

// round 12
// speedup vs baseline: 3.5721x; 1.1206x over previous
#include <cuda_runtime.h>
#include <math.h>
#include <stdint.h>
#include <stddef.h>

#define B_    16
#define T_    257
#define H_    1024
#define V_    1024
#define S_    512
#define E_    512
#define ENC2_ 1024
#define SOS_  1
#define EOS_  2
#define NCTA  128
#define NTHR  512

typedef unsigned long long u64;

// ---------------------------------------------------------------------------
// f32x2 packed-math helpers
// ---------------------------------------------------------------------------
__device__ __forceinline__ u64 pack2(float v) {
    u64 r; asm("mov.b64 %0, {%1, %1};" : "=l"(r) : "f"(v)); return r;
}
__device__ __forceinline__ void ffma2(u64& d, u64 a, u64 b) {
    asm("fma.rn.f32x2 %0, %1, %2, %0;" : "+l"(d) : "l"(a), "l"(b));
}
__device__ __forceinline__ float2 unpack2(u64 v) {
    float2 f; asm("mov.b64 {%0, %1}, %2;" : "=f"(f.x), "=f"(f.y) : "l"(v)); return f;
}

// cp.async helpers: stage 64KB (16384 floats) with 512 threads
__device__ __forceinline__ void stage_async(const float* __restrict__ src,
                                            float* __restrict__ dst, int tid) {
#pragma unroll
    for (int i = 0; i < 8; ++i) {
        unsigned u = (unsigned)__cvta_generic_to_shared(dst + (tid + NTHR * i) * 4);
        asm volatile("cp.async.cg.shared.global [%0], [%1], 16;"
                     :: "r"(u), "l"(src + (tid + NTHR * i) * 4));
    }
    asm volatile("cp.async.commit_group;");
}
template <int N> __device__ __forceinline__ void cp_wait() {
    asm volatile("cp.async.wait_group %0;" :: "n"(N));
}

// ---------------------------------------------------------------------------
// Device scratch (static only)
// ---------------------------------------------------------------------------
__device__ float d_P0[(size_t)V_ * 4096];                 // 16 MB
__device__ float d_Wp[5ull * 128 * 256 * 32 * 4];         // 80 MB packed panels
__device__ float d_hT[3][2][H_ * B_];                     // transposed h: [col][b]
__device__ float d_hs[(size_t)B_ * T_ * H_];
__device__ float d_scores[(size_t)B_ * T_ * S_];
__device__ float d_ctx[(size_t)B_ * T_ * H_];
__device__ float d_hidden[(size_t)B_ * T_ * H_];
__device__ float d_logits[(size_t)B_ * T_ * V_];
__device__ float d_nll[B_ * T_];
__device__ unsigned d_bar_cnt;
__device__ volatile unsigned d_bar_gen;

// ---------------------------------------------------------------------------
__global__ void init_k() {
    int i = blockIdx.x * blockDim.x + threadIdx.x;
    if (i == 0) { d_bar_cnt = 0; d_bar_gen = 0; }
    float* h = &d_hT[0][0][0];
    const int n = 3 * 2 * B_ * H_;
    for (int j = i; j < n; j += gridDim.x * blockDim.x) h[j] = 0.f;
}

// Pack one [4096][1024] matrix into per-CTA panels:
// out[((cta*256 + k4)*32 + lane)*4 + kk] = W[(lane>>3)*1024 + cta*8 + (lane&7)][k4*4+kk]
__global__ void pack_k(const float* __restrict__ W, float* __restrict__ out) {
    const int cta = blockIdx.x, kb = blockIdx.y;   // 128 x 8
    const int lane = threadIdx.x & 31, kq = threadIdx.x >> 5;
    const int j = (lane >> 3) * 1024 + cta * 8 + (lane & 7);
#pragma unroll
    for (int i = 0; i < 4; ++i) {
        int k4 = kb * 32 + kq * 4 + i;
        float4 v = *(const float4*)(W + (size_t)j * 1024 + k4 * 4);
        *(float4*)(out + (((size_t)cta * 256 + k4) * 32 + lane) * 4) = v;
    }
}

// ---------------------------------------------------------------------------
__device__ __forceinline__ void gridsync(unsigned& lgen) {
    __syncthreads();
    if (threadIdx.x == 0) {
        __threadfence();
        unsigned target = ++lgen;
        unsigned arrived = atomicAdd(&d_bar_cnt, 1u) + 1u;
        if (arrived == target * (unsigned)NCTA) {
            d_bar_gen = target;
        } else {
            while (d_bar_gen < target) { }
        }
        __threadfence();
    }
    __syncthreads();
}

__device__ __forceinline__ float sigmoidf_(float x) { return 1.f / (1.f + __expf(-x)); }

// One warp accumulates its 64-k slice of one matrix panel into acc[8] (16 batches)
__device__ __forceinline__ void accum_mat(const float* __restrict__ Wm, int cta,
                                          int kg, int lane,
                                          const float* __restrict__ xs, u64 acc[8]) {
    const float4* wp = (const float4*)Wm + ((size_t)cta * 256 + kg * 16) * 32 + lane;
    const float* xsk = xs + kg * 1024;                    // 64 k * 16 floats
#pragma unroll 4
    for (int k4 = 0; k4 < 16; ++k4) {
        float4 w = wp[(size_t)k4 * 32];
        const ulonglong2* xr = (const ulonglong2*)(xsk + k4 * 64);
#pragma unroll
        for (int kk = 0; kk < 4; ++kk) {
            u64 wv = pack2(((const float*)&w)[kk]);
            ulonglong2 x0 = xr[kk * 4 + 0];
            ulonglong2 x1 = xr[kk * 4 + 1];
            ulonglong2 x2 = xr[kk * 4 + 2];
            ulonglong2 x3 = xr[kk * 4 + 3];
            ffma2(acc[0], wv, x0.x); ffma2(acc[1], wv, x0.y);
            ffma2(acc[2], wv, x1.x); ffma2(acc[3], wv, x1.y);
            ffma2(acc[4], wv, x2.x); ffma2(acc[5], wv, x2.y);
            ffma2(acc[6], wv, x3.x); ffma2(acc[7], wv, x3.y);
        }
    }
}

__device__ __forceinline__ void dump(float* __restrict__ gp, int kg, int lane,
                                     const u64 acc[8]) {
    float* g = gp + (kg * 32 + lane) * 18;
#pragma unroll
    for (int p = 0; p < 8; ++p) *(float2*)(g + 2 * p) = unpack2(acc[p]);
}

// sum of 16 k-warp partials for row = gate*8+uu, batch bb
__device__ __forceinline__ float gate_sum(const float* __restrict__ gp, int row, int bb) {
    float s = 0.f;
#pragma unroll
    for (int k = 0; k < 16; ++k) s += gp[(k * 32 + row) * 18 + bb];
    return s;
}

// quad shuffle butterfly -> full i,f,g,o per lane; gate-0 lane writes state
__device__ __forceinline__ void lstm_update(float s, int gate, float* __restrict__ cptr,
                                            float* __restrict__ h1,
                                            float* __restrict__ h2) {
    float b1v = __shfl_xor_sync(0xffffffffu, s,   1);
    float c2v = __shfl_xor_sync(0xffffffffu, s,   2);
    float d2v = __shfl_xor_sync(0xffffffffu, b1v, 2);
    float g0, g1, g2, g3;
    if      (gate == 0) { g0 = s;   g1 = b1v; g2 = c2v; g3 = d2v; }
    else if (gate == 1) { g0 = b1v; g1 = s;   g2 = d2v; g3 = c2v; }
    else if (gate == 2) { g0 = c2v; g1 = d2v; g2 = s;   g3 = b1v; }
    else                { g0 = d2v; g1 = c2v; g2 = b1v; g3 = s;   }
    float ig = sigmoidf_(g0), fg = sigmoidf_(g1);
    float gt = tanhf(g2),     og = sigmoidf_(g3);
    float cc = fg * (*cptr) + ig * gt;
    float hh = og * tanhf(cc);
    if (gate == 0) {
        *cptr = cc;
        *h1 = hh;
        if (h2) *h2 = hh;
    }
}

// ---------------------------------------------------------------------------
// Persistent LSTM recurrence, WAVEFRONT-PIPELINED across layers:
// wave w computes layer0(t=w), layer1(t=w-1), layer2(t=w-2) concurrently.
// All inputs of a wave were produced before the previous (single) grid barrier.
// smem: xs0[16384] | xs1[16384] | gp[9216] | c_s[384]   (~169 KB)
// ---------------------------------------------------------------------------
__global__ __launch_bounds__(NTHR, 1) void recur_k(const int* __restrict__ tokens,
    const float* __restrict__ bih1, const float* __restrict__ bhh1,
    const float* __restrict__ bih2, const float* __restrict__ bhh2) {

    extern __shared__ float smem[];
    float* xs0 = smem;                   // 16384 floats
    float* xs1 = smem + 16384;           // 16384 floats
    float* gp  = smem + 32768;           // 9216 floats
    float* c_s = smem + 32768 + 9216;    // 384 floats

    const int tid = threadIdx.x, cta = blockIdx.x;
    for (int i = tid; i < 384; i += NTHR) c_s[i] = 0.f;

    const int kg   = tid >> 5, lane = tid & 31;   // GEMM mapping
    const int quad = tid >> 2, gate = tid & 3;    // update mapping
    const int uu   = quad >> 4, bb = quad & 15;
    const int ucol = cta * 8 + uu;
    const int row  = gate * 8 + uu;
    const int jb   = gate * 1024 + ucol;

    const float bL1 = bih1[jb] + bhh1[jb];
    const float bL2 = bih2[jb] + bhh2[jb];

    const size_t MSZ = 128ull * 256 * 32 * 4;
    const float* W0 = d_Wp;                 // Whh0
    const float* W1 = d_Wp + 1 * MSZ;       // Wih1
    const float* W2 = d_Wp + 2 * MSZ;       // Whh1
    const float* W3 = d_Wp + 3 * MSZ;       // Wih2
    const float* W4 = d_Wp + 4 * MSZ;       // Whh2

    unsigned lgen = 0;
    __syncthreads();

    u64 acc0[8], acc1[8], acc2[8];

    // prologue: h0(-1), h1(-1) are zeros in buffer 0
    stage_async(d_hT[0][0], xs0, tid);
    stage_async(d_hT[1][0], xs1, tid);

    for (int w = 0; w < T_ + 2; ++w) {
        const int rb = w & 1, wb = rb ^ 1;
        const bool L0 = (w < T_);              // layer0 time w
        const bool L1 = (w >= 1) && (w <= T_); // layer1 time w-1
        const bool L2 = (w >= 2);              // layer2 time w-2

        // xs0 = h0(prev wave), xs1 = h1(prev wave)
        cp_wait<0>(); __syncthreads();

        if (L0) {
#pragma unroll
            for (int p = 0; p < 8; ++p) acc0[p] = 0ull;
            accum_mat(W0, cta, kg, lane, xs0, acc0);
        }
        if (L1) {
#pragma unroll
            for (int p = 0; p < 8; ++p) acc1[p] = 0ull;
            accum_mat(W1, cta, kg, lane, xs0, acc1);
        }
        __syncthreads();                          // xs0 consumed
        stage_async(d_hT[2][rb], xs0, tid);       // h2(prev wave) -> xs0

        if (L1) accum_mat(W2, cta, kg, lane, xs1, acc1);
        if (L2) {
#pragma unroll
            for (int p = 0; p < 8; ++p) acc2[p] = 0ull;
            accum_mat(W3, cta, kg, lane, xs1, acc2);
        }
        cp_wait<0>(); __syncthreads();            // h2 ready (xs1 also consumed)
        if (L2) accum_mat(W4, cta, kg, lane, xs0, acc2);

        // ---- updates (CTA-local syncs only) ----
        if (L0) {
            dump(gp, kg, lane, acc0);
            __syncthreads();
            int tok = (w == 0) ? SOS_ : tokens[bb * 256 + (w - 1)];
            float s = gate_sum(gp, row, bb) + d_P0[(size_t)tok * 4096 + jb];
            lstm_update(s, gate, &c_s[uu * 16 + bb],
                        &d_hT[0][wb][ucol * 16 + bb], nullptr);
            __syncthreads();
        }
        if (L1) {
            dump(gp, kg, lane, acc1);
            __syncthreads();
            float s = gate_sum(gp, row, bb) + bL1;
            lstm_update(s, gate, &c_s[128 + uu * 16 + bb],
                        &d_hT[1][wb][ucol * 16 + bb], nullptr);
            __syncthreads();
        }
        if (L2) {
            dump(gp, kg, lane, acc2);
            __syncthreads();
            int u = w - 2;
            float s = gate_sum(gp, row, bb) + bL2;
            lstm_update(s, gate, &c_s[256 + uu * 16 + bb],
                        &d_hT[2][wb][ucol * 16 + bb],
                        &d_hs[((size_t)bb * T_ + u) * H_ + ucol]);
            __syncthreads();
        }

        gridsync(lgen);                           // ONE barrier per wave

        if (w + 1 < T_ + 2) {                     // prefetch next wave's h0/h1
            stage_async(d_hT[0][wb], xs0, tid);
            stage_async(d_hT[1][wb], xs1, tid);
        }
    }
}

// ---------------------------------------------------------------------------
// Tiled SGEMM with f32x2 micro-kernel. TRANSB=1: C = A * B^T ; else C = A * B
// ---------------------------------------------------------------------------
template <int TRANSB, int ACCUM, int DOTANH>
__global__ void gemm_k(const float* __restrict__ A, const float* __restrict__ B,
                       float* __restrict__ C,
                       int M, int N, int K, int lda, int ldb, int ldc,
                       long long sA, long long sB, long long sC,
                       const float* __restrict__ bias1,
                       const float* __restrict__ bias2) {
    A += (long long)blockIdx.z * sA;
    B += (long long)blockIdx.z * sB;
    C += (long long)blockIdx.z * sC;

    __shared__ float As[16][68];
    __shared__ float Bs[16][68];

    const int m0 = blockIdx.y * 64, n0 = blockIdx.x * 64;
    const int tid = threadIdx.x;
    const int ty = tid >> 4, tx = tid & 15;
    const int lr = tid >> 2;
    const int lk = (tid & 3) << 2;

    u64 acc2[4][2] = {};

    for (int kt = 0; kt < K; kt += 16) {
        float4 av = make_float4(0.f, 0.f, 0.f, 0.f);
        if (m0 + lr < M) av = *(const float4*)(A + (size_t)(m0 + lr) * lda + kt + lk);
        As[lk + 0][lr] = av.x; As[lk + 1][lr] = av.y;
        As[lk + 2][lr] = av.z; As[lk + 3][lr] = av.w;
        if (TRANSB) {
            float4 bv = *(const float4*)(B + (size_t)(n0 + lr) * ldb + kt + lk);
            Bs[lk + 0][lr] = bv.x; Bs[lk + 1][lr] = bv.y;
            Bs[lk + 2][lr] = bv.z; Bs[lk + 3][lr] = bv.w;
        } else {
            int bk = tid >> 4, bn = (tid & 15) << 2;
            float4 bv = *(const float4*)(B + (size_t)(kt + bk) * ldb + n0 + bn);
            *(float4*)&Bs[bk][bn] = bv;
        }
        __syncthreads();
#pragma unroll
        for (int kk = 0; kk < 16; ++kk) {
            float4 a = *(const float4*)&As[kk][ty << 2];
            ulonglong2 b2 = *(const ulonglong2*)&Bs[kk][tx << 2];
            u64 a0 = pack2(a.x), a1 = pack2(a.y), a2 = pack2(a.z), a3 = pack2(a.w);
            ffma2(acc2[0][0], a0, b2.x); ffma2(acc2[0][1], a0, b2.y);
            ffma2(acc2[1][0], a1, b2.x); ffma2(acc2[1][1], a1, b2.y);
            ffma2(acc2[2][0], a2, b2.x); ffma2(acc2[2][1], a2, b2.y);
            ffma2(acc2[3][0], a3, b2.x); ffma2(acc2[3][1], a3, b2.y);
        }
        __syncthreads();
    }

#pragma unroll
    for (int i = 0; i < 4; ++i) {
        int m = m0 + (ty << 2) + i;
        if (m >= M) continue;
        float vj[4];
        float2 u0 = unpack2(acc2[i][0]), u1 = unpack2(acc2[i][1]);
        vj[0] = u0.x; vj[1] = u0.y; vj[2] = u1.x; vj[3] = u1.y;
#pragma unroll
        for (int j = 0; j < 4; ++j) {
            int n = n0 + (tx << 2) + j;
            float v = vj[j];
            if (ACCUM) v += C[(size_t)m * ldc + n];
            if (bias1) v += bias1[n];
            if (bias2) v += bias2[n];
            if (DOTANH) v = tanhf(v);
            C[(size_t)m * ldc + n] = v;
        }
    }
}

// ---------------------------------------------------------------------------
__global__ void softmax_k() {
    __shared__ float red[256];
    const int tid = threadIdx.x;
    float* x = d_scores + (size_t)blockIdx.x * S_;
    float m = fmaxf(x[tid], x[tid + 256]);
    red[tid] = m; __syncthreads();
    for (int s = 128; s > 0; s >>= 1) {
        if (tid < s) red[tid] = fmaxf(red[tid], red[tid + s]);
        __syncthreads();
    }
    m = red[0]; __syncthreads();
    float e0 = __expf(x[tid] - m), e1 = __expf(x[tid + 256] - m);
    red[tid] = e0 + e1; __syncthreads();
    for (int s = 128; s > 0; s >>= 1) {
        if (tid < s) red[tid] += red[tid + s];
        __syncthreads();
    }
    float inv = 1.f / red[0];
    x[tid] = e0 * inv;
    x[tid + 256] = e1 * inv;
}

__global__ void nll_k(const int* __restrict__ tokens) {
    __shared__ float red[256];
    const int tid = threadIdx.x;
    const int row = blockIdx.x;
    const int b = row / T_, t = row % T_;
    const float* x = d_logits + (size_t)row * V_;
    float m = -1e30f;
    for (int i = tid; i < V_; i += 256) m = fmaxf(m, x[i]);
    red[tid] = m; __syncthreads();
    for (int s = 128; s > 0; s >>= 1) {
        if (tid < s) red[tid] = fmaxf(red[tid], red[tid + s]);
        __syncthreads();
    }
    m = red[0]; __syncthreads();
    float sum = 0.f;
    for (int i = tid; i < V_; i += 256) sum += __expf(x[i] - m);
    red[tid] = sum; __syncthreads();
    for (int s = 128; s > 0; s >>= 1) {
        if (tid < s) red[tid] += red[tid + s];
        __syncthreads();
    }
    if (tid == 0) {
        int tgt = (t < 256) ? tokens[b * 256 + t] : EOS_;
        d_nll[row] = m + logf(red[0]) - x[tgt];
    }
}

__global__ void mean_k(float* __restrict__ out) {
    __shared__ float red[256];
    const int tid = threadIdx.x;
    float s = 0.f;
    for (int i = tid; i < B_ * T_; i += 256) s += d_nll[i];
    red[tid] = s; __syncthreads();
    for (int st = 128; st > 0; st >>= 1) {
        if (tid < st) red[tid] += red[tid + st];
        __syncthreads();
    }
    if (tid == 0) out[0] = red[0] / (float)(B_ * T_);
}

// ---------------------------------------------------------------------------
extern "C" void kernel_launch(void* const* d_in, const int* in_sizes, int n_in,
                              void* d_out, int out_size) {
    const int*   tokens = (const int*)  d_in[0];
    const float* enc    = (const float*)d_in[1];
    const float* emb    = (const float*)d_in[2];
    const float* Wih0   = (const float*)d_in[3];
    const float* Whh0   = (const float*)d_in[4];
    const float* bih0   = (const float*)d_in[5];
    const float* bhh0   = (const float*)d_in[6];
    const float* Wih1   = (const float*)d_in[7];
    const float* Whh1   = (const float*)d_in[8];
    const float* bih1   = (const float*)d_in[9];
    const float* bhh1   = (const float*)d_in[10];
    const float* Wih2   = (const float*)d_in[11];
    const float* Whh2   = (const float*)d_in[12];
    const float* bih2   = (const float*)d_in[13];
    const float* bhh2   = (const float*)d_in[14];
    const float* W1     = (const float*)d_in[15];
    const float* b1     = (const float*)d_in[16];
    const float* W2     = (const float*)d_in[17];
    const float* b2     = (const float*)d_in[18];
    float* out = (float*)d_out;

    float* P0;      cudaGetSymbolAddress((void**)&P0,      d_P0);
    float* Wp;      cudaGetSymbolAddress((void**)&Wp,      d_Wp);
    float* hs;      cudaGetSymbolAddress((void**)&hs,      d_hs);
    float* scores;  cudaGetSymbolAddress((void**)&scores,  d_scores);
    float* ctx;     cudaGetSymbolAddress((void**)&ctx,     d_ctx);
    float* hidden;  cudaGetSymbolAddress((void**)&hidden,  d_hidden);
    float* logits;  cudaGetSymbolAddress((void**)&logits,  d_logits);

    const int RSMEM = (32768 + 9216 + 384) * 4;
    static int smem_set = 0;
    if (!smem_set) {
        cudaFuncSetAttribute(recur_k, cudaFuncAttributeMaxDynamicSharedMemorySize, RSMEM);
        smem_set = 1;
    }

    init_k<<<192, 256>>>();

    // pack the 5 recurrent matrices into panels
    const size_t MSZ = 128ull * 256 * 32 * 4;
    pack_k<<<dim3(128, 8), 256>>>(Whh0, Wp + 0 * MSZ);
    pack_k<<<dim3(128, 8), 256>>>(Wih1, Wp + 1 * MSZ);
    pack_k<<<dim3(128, 8), 256>>>(Whh1, Wp + 2 * MSZ);
    pack_k<<<dim3(128, 8), 256>>>(Wih2, Wp + 3 * MSZ);
    pack_k<<<dim3(128, 8), 256>>>(Whh2, Wp + 4 * MSZ);

    // P0[v][j] = emb[v] . Wih0[j][:E] + bih0[j] + bhh0[j]
    gemm_k<1,0,0><<<dim3(64, 16, 1), 256>>>(
        emb, Wih0, P0, 1024, 4096, 512, 512, 1536, 4096, 0, 0, 0, bih0, bhh0);

    // persistent wavefront recurrence
    recur_k<<<NCTA, NTHR, RSMEM>>>(tokens, bih1, bhh1, bih2, bhh2);

    // attention scores: [b] hs[257,1024] * enc[512,1024]^T
    gemm_k<1,0,0><<<dim3(8, 5, 16), 256>>>(
        hs, enc, scores, T_, S_, H_, H_, ENC2_, S_,
        (long long)T_ * H_, (long long)S_ * ENC2_, (long long)T_ * S_,
        nullptr, nullptr);

    softmax_k<<<B_ * T_, 256>>>();

    // context: [b] probs[257,512] * enc[512,1024]
    gemm_k<0,0,0><<<dim3(16, 5, 16), 256>>>(
        scores, enc, ctx, T_, ENC2_, S_, S_, ENC2_, ENC2_,
        (long long)T_ * S_, (long long)S_ * ENC2_, (long long)T_ * ENC2_,
        nullptr, nullptr);

    // hidden = tanh(hs @ W1[:, :H]^T + ctx @ W1[:, H:]^T + b1)
    gemm_k<1,0,0><<<dim3(16, 65, 1), 256>>>(
        hs, W1, hidden, B_ * T_, H_, H_, H_, 2048, H_, 0, 0, 0,
        nullptr, nullptr);
    gemm_k<1,1,1><<<dim3(16, 65, 1), 256>>>(
        ctx, W1 + 1024, hidden, B_ * T_, H_, ENC2_, ENC2_, 2048, H_, 0, 0, 0,
        b1, nullptr);

    // logits = hidden @ W2^T + b2
    gemm_k<1,0,0><<<dim3(16, 65, 1), 256>>>(
        hidden, W2, logits, B_ * T_, V_, H_, H_, H_, V_, 0, 0, 0,
        b2, nullptr);

    nll_k<<<B_ * T_, 256>>>(tokens);
    mean_k<<<1, 256>>>(out);
}